// round 2
// baseline (speedup 1.0000x reference)
#include <cuda_runtime.h>

#define GS 32
#define G3 32768
#define BATCH 256
#define NPTS 4096
#define THREADS 512
#define PTS_PER_THREAD (NPTS / THREADS)   // 8
#define NWARPS (THREADS / 32)             // 16
#define NWORDS (G3 / 32)                  // 1024

__global__ void zero_kernel(float* out, int n) {
    int i = blockIdx.x * blockDim.x + threadIdx.x;
    if (i < n) out[i] = 0.f;
}

__global__ __launch_bounds__(THREADS, 2) void symloss_kernel(
    const float* __restrict__ points,
    const float* __restrict__ cp,
    const float* __restrict__ voxel,
    const float* __restrict__ plane,
    const float* __restrict__ quat,
    float* __restrict__ out)
{
    __shared__ float tf[6][12];            // per-transform affine: m[9], t[3]
    __shared__ unsigned bitmap[NWORDS];    // voxel occupancy bitmap (4KB)

    int tid = threadIdx.x;
    int wid = tid >> 5, lid = tid & 31;
    int b = blockIdx.x;

    // --- build the 6 affine transforms (p' = M p + t) ---
    if (tid < 6) {
        float m[9], t[3];
        if (tid < 3) {
            const float* p = plane + tid * 4;
            float nx = p[0], ny = p[1], nz = p[2], d = p[3];
            float k = 2.0f / (nx*nx + ny*ny + nz*nz);
            m[0] = 1.f - k*nx*nx; m[1] = -k*nx*ny;       m[2] = -k*nx*nz;
            m[3] = -k*ny*nx;      m[4] = 1.f - k*ny*ny;  m[5] = -k*ny*nz;
            m[6] = -k*nz*nx;      m[7] = -k*nz*ny;       m[8] = 1.f - k*nz*nz;
            t[0] = -k*d*nx; t[1] = -k*d*ny; t[2] = -k*d*nz;
        } else {
            const float* q = quat + (tid - 3) * 4;
            float qn = rsqrtf(q[0]*q[0] + q[1]*q[1] + q[2]*q[2] + q[3]*q[3]);
            float w = q[0]*qn, ux = q[1]*qn, uy = q[2]*qn, uz = q[3]*qn;
            m[0] = 1.f - 2.f*(uy*uy + uz*uz); m[1] = 2.f*(ux*uy - w*uz);        m[2] = 2.f*(ux*uz + w*uy);
            m[3] = 2.f*(ux*uy + w*uz);        m[4] = 1.f - 2.f*(ux*ux + uz*uz); m[5] = 2.f*(uy*uz - w*ux);
            m[6] = 2.f*(ux*uz - w*uy);        m[7] = 2.f*(uy*uz + w*ux);        m[8] = 1.f - 2.f*(ux*ux + uy*uy);
            t[0] = t[1] = t[2] = 0.f;
        }
        #pragma unroll
        for (int j = 0; j < 9; j++) tf[tid][j] = m[j];
        #pragma unroll
        for (int j = 0; j < 3; j++) tf[tid][9 + j] = t[j];
    }

    // --- build voxel bitmap for this batch (coalesced loads + ballot) ---
    const float* vb = voxel + (size_t)b * G3;
    for (int w = wid; w < NWORDS; w += NWARPS) {
        float v = vb[w * 32 + lid];
        unsigned bits = __ballot_sync(0xffffffffu, v > 0.5f);
        if (lid == 0) bitmap[w] = bits;
    }
    __syncthreads();

    const float* pbase = points + (size_t)b * NPTS * 3;
    const float* cpb   = cp + (size_t)b * G3 * 3;
    const float GMIN = -0.484375f;  // -0.5 + 0.5/32

    float accP = 0.f, accR = 0.f;

    // point-outer: load each point once, run all 6 gathers (high MLP)
    for (int it = 0; it < PTS_PER_THREAD; it++) {
        int n = tid + it * THREADS;
        float x = pbase[n*3 + 0];
        float y = pbase[n*3 + 1];
        float z = pbase[n*3 + 2];

        #pragma unroll
        for (int s = 0; s < 6; s++) {
            float px = fmaf(tf[s][0], x, fmaf(tf[s][1], y, fmaf(tf[s][2], z, tf[s][9])));
            float py = fmaf(tf[s][3], x, fmaf(tf[s][4], y, fmaf(tf[s][5], z, tf[s][10])));
            float pz = fmaf(tf[s][6], x, fmaf(tf[s][7], y, fmaf(tf[s][8], z, tf[s][11])));
            float ix = rintf(fminf(fmaxf((px - GMIN) * 32.f, 0.f), 31.f));
            float iy = rintf(fminf(fmaxf((py - GMIN) * 32.f, 0.f), 31.f));
            float iz = rintf(fminf(fmaxf((pz - GMIN) * 32.f, 0.f), 31.f));
            int idx = (int)ix * 1024 + (int)iy * 32 + (int)iz;

            unsigned word = bitmap[idx >> 5];
            bool open = ((word >> (idx & 31)) & 1u) == 0u;   // voxel==0 -> mask=1

            float d2 = 0.f;
            if (open) {   // predicated: masked lanes skip the 3 cp loads entirely
                const float* c = cpb + (size_t)idx * 3;
                float dx = px - __ldg(c + 0);
                float dy = py - __ldg(c + 1);
                float dz = pz - __ldg(c + 2);
                d2 = fmaf(dx, dx, fmaf(dy, dy, dz * dz));
            }
            if (s < 3) accP += d2; else accR += d2;
        }
    }

    // --- block reduction ---
    #pragma unroll
    for (int off = 16; off > 0; off >>= 1) {
        accP += __shfl_down_sync(0xffffffffu, accP, off);
        accR += __shfl_down_sync(0xffffffffu, accR, off);
    }
    __shared__ float redP[NWARPS], redR[NWARPS];
    if (lid == 0) { redP[wid] = accP; redR[wid] = accR; }
    __syncthreads();
    if (wid == 0) {
        accP = (lid < NWARPS) ? redP[lid] : 0.f;
        accR = (lid < NWARPS) ? redR[lid] : 0.f;
        #pragma unroll
        for (int off = 8; off > 0; off >>= 1) {
            accP += __shfl_down_sync(0xffffffffu, accP, off);
            accR += __shfl_down_sync(0xffffffffu, accR, off);
        }
        if (lid == 0) {
            atomicAdd(out + 0, accP * (1.0f / BATCH));
            atomicAdd(out + 1, accR * (1.0f / BATCH));
        }
    }
}

extern "C" void kernel_launch(void* const* d_in, const int* in_sizes, int n_in,
                              void* d_out, int out_size) {
    const float* points = (const float*)d_in[0];
    const float* cp     = (const float*)d_in[1];
    const float* voxel  = (const float*)d_in[2];
    const float* plane  = (const float*)d_in[3];
    const float* quat   = (const float*)d_in[4];
    float* out = (float*)d_out;

    zero_kernel<<<(out_size + 255) / 256, 256>>>(out, out_size);
    symloss_kernel<<<BATCH, THREADS>>>(points, cp, voxel, plane, quat, out);
}